// round 15
// baseline (speedup 1.0000x reference)
#include <cuda_runtime.h>
#include <cuda_fp16.h>
#include <cstdint>
#include <math.h>

#define NN 50000
#define NE 800000
#define INDIM 128
#define HID 64
#define NSCH 49   // ceil(NN/1024)

// ======================= device scratch =======================
__device__ int   g_deg[NN];           // static-zeroed; re-zeroed by k_scan23
__device__ int   g_row_start[NN + 1];
__device__ int   g_cursor[NN];
__device__ int   g_csr[NE];
__device__ float g_invdeg[NN];
__device__ int   g_psum[64];
__device__ float g_y[NN * HID];
__device__ float g_h1[NN * HID];
__device__ float g_y2[NN * HID];
__device__ float g_zeros[128];

// ======================= packed f32x2 helpers =======================
#define FMA2(c, a, b) asm("fma.rn.f32x2 %0, %1, %2, %3;" \
                          : "=l"(c) : "l"(a), "l"(b), "l"(c))
__device__ __forceinline__ unsigned long long pk(float lo, float hi) {
    unsigned long long r = (unsigned long long)__float_as_uint(lo);
    return r | ((unsigned long long)__float_as_uint(hi) << 32);
}

#define GRT 40
#define GNT 320
#define G1BLK (NN / GRT)      // 1250 gemm blocks in FK1
#define CNTBLK (NE / GNT)     // 2500 count blocks in FK1

// ============ FK1: fused [gemm layer1 (y = x@W1)] + [edge-count histogram] ============
__global__ void __launch_bounds__(GNT) k_fk1(const float* __restrict__ Z,
                                             const float* __restrict__ W,
                                             const int* __restrict__ dstE,
                                             float* __restrict__ out) {
    if (blockIdx.x >= G1BLK) {
        int e = (blockIdx.x - G1BLK) * GNT + threadIdx.x;
        if (e < NE) atomicAdd(&g_deg[dstE[e]], 1);
        return;
    }
    constexpr int K = INDIM;
    constexpr int KP = K + 4;
    constexpr int PSTR = 2 * K + 8;
    extern __shared__ float smg[];
    float* Ws  = smg;
    float* Zs2 = smg + 64 * KP;
    int tid = threadIdx.x;
    int j = tid % 64, rg = tid / 64;
    for (int idx = tid; idx < K * 64; idx += GNT) {
        int k = idx >> 6, c = idx & 63;
        Ws[c * KP + k] = W[idx];
    }
    int row0 = blockIdx.x * GRT;
    for (int idx = tid; idx < GRT * (K / 4); idx += GNT) {
        int r = idx / (K / 4), kq = idx % (K / 4);
        float4 v = reinterpret_cast<const float4*>(Z + (size_t)(row0 + r) * K)[kq];
        float* zb = Zs2 + (r >> 1) * PSTR + (r & 1) + 8 * kq;
        zb[0] = v.x; zb[2] = v.y; zb[4] = v.z; zb[6] = v.w;
    }
    __syncthreads();
    unsigned long long acc2[4];
    #pragma unroll
    for (int rp = 0; rp < 4; rp++) acc2[rp] = 0ull;
    const float4* w4 = reinterpret_cast<const float4*>(&Ws[j * KP]);
    #pragma unroll 8
    for (int k4 = 0; k4 < K / 4; k4++) {
        float4 w = w4[k4];
        unsigned long long w0 = pk(w.x, w.x), w1 = pk(w.y, w.y);
        unsigned long long w2 = pk(w.z, w.z), w3 = pk(w.w, w.w);
        #pragma unroll
        for (int rp = 0; rp < 4; rp++) {
            const ulonglong2* zp = reinterpret_cast<const ulonglong2*>(
                &Zs2[(rg * 4 + rp) * PSTR + 8 * k4]);
            ulonglong2 A = zp[0], B = zp[1];
            FMA2(acc2[rp], A.x, w0);
            FMA2(acc2[rp], A.y, w1);
            FMA2(acc2[rp], B.x, w2);
            FMA2(acc2[rp], B.y, w3);
        }
    }
    #pragma unroll
    for (int rp = 0; rp < 4; rp++) {
        float lo = __uint_as_float((unsigned)acc2[rp]);
        float hi = __uint_as_float((unsigned)(acc2[rp] >> 32));
        out[(size_t)(row0 + rg * 8 + 2 * rp) * 64 + j]     = lo;
        out[(size_t)(row0 + rg * 8 + 2 * rp + 1) * 64 + j] = hi;
    }
}

// ======================= CSR scan (two launches, proven R12 path) =======================
__global__ void __launch_bounds__(1024) k_scan1() {
    __shared__ int wsum[32];
    int tid = threadIdx.x;
    int i = blockIdx.x * 1024 + tid;
    int v = (i < NN) ? g_deg[i] : 0;
    int xv = v;
    #pragma unroll
    for (int o = 1; o < 32; o <<= 1) {
        int y = __shfl_up_sync(0xffffffffu, xv, o);
        if ((tid & 31) >= o) xv += y;
    }
    if ((tid & 31) == 31) wsum[tid >> 5] = xv;
    __syncthreads();
    if (tid < 32) {
        int s = wsum[tid];
        #pragma unroll
        for (int o = 1; o < 32; o <<= 1) {
            int y = __shfl_up_sync(0xffffffffu, s, o);
            if (tid >= o) s += y;
        }
        wsum[tid] = s;
    }
    __syncthreads();
    int add = (tid >= 32) ? wsum[(tid >> 5) - 1] : 0;
    if (i < NN) g_row_start[i] = xv + add - v;
    if (tid == 0) g_psum[blockIdx.x] = wsum[31];
}

// Fused: scan the 49 chunk sums (redundantly per block) + apply + init + deg reset.
__global__ void __launch_bounds__(1024) k_scan23() {
    __shared__ int sexc[64];
    __shared__ int wtot;
    int tid = threadIdx.x;
    int v = 0, x = 0;
    if (tid < 64) {
        v = (tid < NSCH) ? g_psum[tid] : 0;
        x = v;
        #pragma unroll
        for (int o = 1; o < 32; o <<= 1) {
            int y = __shfl_up_sync(0xffffffffu, x, o);
            if ((tid & 31) >= o) x += y;
        }
        if (tid == 31) wtot = x;
    }
    __syncthreads();
    if (tid < 64) {
        int incl = x + ((tid >= 32) ? wtot : 0);
        sexc[tid] = incl - v;
        if (tid == NSCH - 1) g_row_start[NN] = incl;
    }
    __syncthreads();
    int off = sexc[blockIdx.x];
    int i = blockIdx.x * 1024 + tid;
    if (i < NN) {
        int rs = g_row_start[i] + off;
        g_row_start[i] = rs;
        g_cursor[i]    = rs;
        g_invdeg[i]    = 1.0f / fmaxf((float)g_deg[i], 1.0f);
        g_deg[i]       = 0;   // reset for next launch (deterministic)
    }
}

__global__ void __launch_bounds__(1024) k_bucket(const int* __restrict__ src,
                                                 const int* __restrict__ dst) {
    int e = blockIdx.x * 1024 + threadIdx.x;
    if (e < NE) {
        int d = dst[e];
        int p = atomicAdd(&g_cursor[d], 1);
        g_csr[p] = src[e];
    }
}

// ======= mean aggregation (fused bias + relu): out = relu(y + agg(y)/deg + b)
__global__ void __launch_bounds__(256) k_aggr(const float* __restrict__ y,
                                              const float* __restrict__ bias,
                                              float* __restrict__ out) {
    int node = blockIdx.x * 16 + (threadIdx.x >> 4);
    int c4 = (threadIdx.x & 15) * 4;
    int beg = g_row_start[node], end = g_row_start[node + 1];
    float4 acc = make_float4(0.f, 0.f, 0.f, 0.f);
    int e = beg;
    for (; e + 7 < end; e += 8) {
        int sI[8];
        #pragma unroll
        for (int u = 0; u < 8; u++) sI[u] = __ldg(&g_csr[e + u]);
        float4 v[8];
        #pragma unroll
        for (int u = 0; u < 8; u++)
            v[u] = *reinterpret_cast<const float4*>(y + (size_t)sI[u] * 64 + c4);
        #pragma unroll
        for (int u = 0; u < 8; u++) {
            acc.x += v[u].x; acc.y += v[u].y;
            acc.z += v[u].z; acc.w += v[u].w;
        }
    }
    for (; e < end; e++) {
        int s = __ldg(&g_csr[e]);
        float4 v = *reinterpret_cast<const float4*>(y + (size_t)s * 64 + c4);
        acc.x += v.x; acc.y += v.y; acc.z += v.z; acc.w += v.w;
    }
    float inv = g_invdeg[node];
    float4 self = *reinterpret_cast<const float4*>(y + (size_t)node * 64 + c4);
    float4 b = *reinterpret_cast<const float4*>(bias + c4);
    float4 r;
    r.x = fmaxf(self.x + acc.x * inv + b.x, 0.0f);
    r.y = fmaxf(self.y + acc.y * inv + b.y, 0.0f);
    r.z = fmaxf(self.z + acc.z * inv + b.z, 0.0f);
    r.w = fmaxf(self.w + acc.w * inv + b.w, 0.0f);
    *reinterpret_cast<float4*>(out + (size_t)node * 64 + c4) = r;
}

// ============ dense GEMM (layer 2) with packed f32x2 ============
template <int K>
__global__ void __launch_bounds__(GNT) k_gemm(const float* __restrict__ Z,
                                              const float* __restrict__ W,
                                              const float* __restrict__ bias,
                                              float* __restrict__ out) {
    constexpr int KP = K + 4;
    constexpr int PSTR = 2 * K + 8;
    extern __shared__ float smg[];
    float* Ws  = smg;
    float* Zs2 = smg + 64 * KP;
    int tid = threadIdx.x;
    int j = tid % 64, rg = tid / 64;
    for (int idx = tid; idx < K * 64; idx += GNT) {
        int k = idx >> 6, c = idx & 63;
        Ws[c * KP + k] = W[idx];
    }
    int row0 = blockIdx.x * GRT;
    for (int idx = tid; idx < GRT * (K / 4); idx += GNT) {
        int r = idx / (K / 4), kq = idx % (K / 4);
        float4 v = reinterpret_cast<const float4*>(Z + (size_t)(row0 + r) * K)[kq];
        float* zb = Zs2 + (r >> 1) * PSTR + (r & 1) + 8 * kq;
        zb[0] = v.x; zb[2] = v.y; zb[4] = v.z; zb[6] = v.w;
    }
    __syncthreads();
    float bj = bias[j];
    unsigned long long acc2[4];
    #pragma unroll
    for (int rp = 0; rp < 4; rp++) acc2[rp] = pk(bj, bj);
    const float4* w4 = reinterpret_cast<const float4*>(&Ws[j * KP]);
    #pragma unroll 8
    for (int k4 = 0; k4 < K / 4; k4++) {
        float4 w = w4[k4];
        unsigned long long w0 = pk(w.x, w.x), w1 = pk(w.y, w.y);
        unsigned long long w2 = pk(w.z, w.z), w3 = pk(w.w, w.w);
        #pragma unroll
        for (int rp = 0; rp < 4; rp++) {
            const ulonglong2* zp = reinterpret_cast<const ulonglong2*>(
                &Zs2[(rg * 4 + rp) * PSTR + 8 * k4]);
            ulonglong2 A = zp[0], B = zp[1];
            FMA2(acc2[rp], A.x, w0);
            FMA2(acc2[rp], A.y, w1);
            FMA2(acc2[rp], B.x, w2);
            FMA2(acc2[rp], B.y, w3);
        }
    }
    #pragma unroll
    for (int rp = 0; rp < 4; rp++) {
        float lo = __uint_as_float((unsigned)acc2[rp]);
        float hi = __uint_as_float((unsigned)(acc2[rp] >> 32));
        out[(size_t)(row0 + rg * 8 + 2 * rp) * 64 + j]     = lo;
        out[(size_t)(row0 + rg * 8 + 2 * rp + 1) * 64 + j] = hi;
    }
}

// ======================= fused edge MLP: interleaved-convert pipelined mma.sync ======
#define ET 128
#define ETILES (NE / ET)         // 6250
#define ROWB 528                 // A row: 264 halfs (8-half pad)
#define RAWB 544                 // raw: hs 256B @0, hd 256B @272
#define OFF_A0 1024
#define OFF_A1 (OFF_A0 + 128 * ROWB)         // 68608
#define OFF_RAW (OFF_A1 + 128 * ROWB)        // 136192
#define SMEM_EDGE (OFF_RAW + 128 * RAWB)     // 205824

__device__ __forceinline__ uint32_t smem_u32(const void* p) {
    uint32_t a;
    asm("{ .reg .u64 t; cvta.to.shared.u64 t, %1; cvt.u32.u64 %0, t; }"
        : "=r"(a) : "l"(p));
    return a;
}

#define CP16(d, s) asm volatile("cp.async.cg.shared.global [%0], [%1], 16;" \
                                :: "r"(d), "l"(s))
#define CP_COMMIT() asm volatile("cp.async.commit_group;" ::: "memory")
#define CP_WAIT0()  asm volatile("cp.async.wait_group 0;" ::: "memory")

#define LDSM4(r, addr)                                                         \
    asm volatile("ldmatrix.sync.aligned.m8n8.x4.shared.b16 {%0,%1,%2,%3}, [%4];" \
                 : "=r"((r)[0]), "=r"((r)[1]), "=r"((r)[2]), "=r"((r)[3])      \
                 : "r"(addr))

#define MMA16816(d, a, b)                                                      \
    asm volatile("mma.sync.aligned.m16n8k16.row.col.f32.f16.f16.f32 "          \
                 "{%0,%1,%2,%3},{%4,%5,%6,%7},{%8,%9},{%0,%1,%2,%3};"          \
                 : "+f"((d)[0]), "+f"((d)[1]), "+f"((d)[2]), "+f"((d)[3])      \
                 : "r"((a)[0]), "r"((a)[1]), "r"((a)[2]), "r"((a)[3]),         \
                   "r"((b)[0]), "r"((b)[1]))

__device__ __forceinline__ void write8h(char* ah, int koff2, const float* v) {
    uint32_t hi[4];
    #pragma unroll
    for (int i = 0; i < 4; i++) {
        __half2 h = __floats2half2_rn(v[2 * i], v[2 * i + 1]);
        hi[i] = *reinterpret_cast<uint32_t*>(&h);
    }
    *reinterpret_cast<uint4*>(ah + koff2) = make_uint4(hi[0], hi[1], hi[2], hi[3]);
}

__device__ __forceinline__ void conv_chunk(const char* rawB, char* rA,
                                           int el, int q, int c) {
    const float4* rhs = reinterpret_cast<const float4*>(rawB + el * RAWB + q * 128);
    const float4* rhd = reinterpret_cast<const float4*>(rawB + el * RAWB + 272 + q * 128);
    float4 a0 = rhs[2 * c], a1 = rhs[2 * c + 1];
    float4 b0 = rhd[2 * c], b1 = rhd[2 * c + 1];
    float hs8[8] = {a0.x, a0.y, a0.z, a0.w, a1.x, a1.y, a1.z, a1.w};
    float hd8[8] = {b0.x, b0.y, b0.z, b0.w, b1.x, b1.y, b1.z, b1.w};
    float p8[8], q8[8];
    #pragma unroll
    for (int i = 0; i < 8; i++) {
        p8[i] = hs8[i] * hd8[i];
        q8[i] = fabsf(hs8[i] - hd8[i]);
    }
    int kb = (32 * q + 8 * c) * 2;
    write8h(rA, kb, hs8);
    write8h(rA, kb + 128, hd8);
    write8h(rA, kb + 256, p8);
    write8h(rA, kb + 384, q8);
}

__global__ void __launch_bounds__(256, 1) k_edge(
    const float* __restrict__ H, const int* __restrict__ src,
    const int* __restrict__ dst, const float* __restrict__ We1,
    const float* __restrict__ be1, const float* __restrict__ We2,
    const float* __restrict__ be2,
    float* __restrict__ logits, float* __restrict__ probs) {
    extern __shared__ char sm[];
    float* sred = reinterpret_cast<float*>(sm);
    char* A0B  = sm + OFF_A0;
    char* A1B  = sm + OFF_A1;
    char* rawB = sm + OFF_RAW;

    int tid = threadIdx.x, lane = tid & 31, wid = tid >> 5;
    int mw = wid & 3, nw = wid >> 2;

    uint32_t bF[16][4][2];
    #pragma unroll
    for (int s = 0; s < 16; s++)
        #pragma unroll
        for (int j = 0; j < 4; j++)
            #pragma unroll
            for (int r = 0; r < 2; r++) {
                int k = s * 16 + 2 * (lane & 3) + r * 8;
                int n = nw * 32 + j * 8 + (lane >> 2);
                __half2 h = __floats2half2_rn(__ldg(&We1[k * 64 + n]),
                                              __ldg(&We1[(k + 1) * 64 + n]));
                bF[s][j][r] = *reinterpret_cast<uint32_t*>(&h);
            }
    float bb[4][2], ww[4][2];
    #pragma unroll
    for (int j = 0; j < 4; j++)
        #pragma unroll
        for (int c = 0; c < 2; c++) {
            int nc = nw * 32 + j * 8 + 2 * (lane & 3) + c;
            bb[j][c] = __ldg(&be1[nc]);
            ww[j][c] = __ldg(&We2[nc]);
        }
    float be2v = be2[0];

    int el = tid >> 1, q = tid & 1;
    const int* idxp = q ? dst : src;
    uint32_t rawDst = smem_u32(rawB + el * RAWB + q * 272);
    uint32_t Aaddr[2] = {smem_u32(A0B), smem_u32(A1B)};
    char* Abuf[2] = {A0B, A1B};
    uint32_t mrow = (uint32_t)(mw * 32 + (lane & 15)) * ROWB + (lane >> 4) * 16;
    int G = gridDim.x;

    int tile0 = blockIdx.x;
    {
        int n0 = __ldg(&idxp[tile0 * ET + el]);
        const char* s0 = (const char*)(H + (size_t)n0 * 64);
        #pragma unroll
        for (int k = 0; k < 16; k++) CP16(rawDst + k * 16, s0 + k * 16);
        CP_COMMIT();
    }
    int t1 = tile0 + G;
    int n1 = (t1 < ETILES) ? __ldg(&idxp[t1 * ET + el]) : 0;
    CP_WAIT0();
    __syncthreads();
    {
        char* rA = A0B + el * ROWB;
        #pragma unroll
        for (int c = 0; c < 4; c++) conv_chunk(rawB, rA, el, q, c);
    }
    __syncthreads();
    if (t1 < ETILES) {
        const char* sN = (const char*)(H + (size_t)n1 * 64);
        #pragma unroll
        for (int k = 0; k < 16; k++) CP16(rawDst + k * 16, sN + k * 16);
        CP_COMMIT();
    }
    int t2 = t1 + G;
    int n2 = (t2 < ETILES) ? __ldg(&idxp[t2 * ET + el]) : 0;

    int b = 0;
    for (int tile = tile0; tile < ETILES; tile += G) {
        int e0 = tile * ET;
        int hasNext = (tile + G < ETILES);
        CP_WAIT0();
        __syncthreads();

        float dacc[2][4][4];
        #pragma unroll
        for (int t = 0; t < 2; t++)
            #pragma unroll
            for (int j = 0; j < 4; j++)
                #pragma unroll
                for (int r = 0; r < 4; r++) dacc[t][j][r] = 0.0f;

        uint32_t base = Aaddr[b] + mrow;
        char* rAother = Abuf[b ^ 1] + el * ROWB;
        #pragma unroll
        for (int s = 0; s < 16; s++) {
            uint32_t a0[4], a1[4];
            LDSM4(a0, base + s * 32);
            LDSM4(a1, base + 16 * ROWB + s * 32);
            #pragma unroll
            for (int j = 0; j < 4; j++) {
                MMA16816(dacc[0][j], a0, bF[s][j]);
                MMA16816(dacc[1][j], a1, bF[s][j]);
            }
            if ((s & 3) == 0 && hasNext)
                conv_chunk(rawB, rAother, el, q, s >> 2);
        }

        #pragma unroll
        for (int t = 0; t < 2; t++) {
            float p0 = 0.0f, p1 = 0.0f;
            #pragma unroll
            for (int j = 0; j < 4; j++) {
                p0 += fmaxf(dacc[t][j][0] + bb[j][0], 0.0f) * ww[j][0];
                p0 += fmaxf(dacc[t][j][1] + bb[j][1], 0.0f) * ww[j][1];
                p1 += fmaxf(dacc[t][j][2] + bb[j][0], 0.0f) * ww[j][0];
                p1 += fmaxf(dacc[t][j][3] + bb[j][1], 0.0f) * ww[j][1];
            }
            p0 += __shfl_xor_sync(0xffffffffu, p0, 1);
            p0 += __shfl_xor_sync(0xffffffffu, p0, 2);
            p1 += __shfl_xor_sync(0xffffffffu, p1, 1);
            p1 += __shfl_xor_sync(0xffffffffu, p1, 2);
            if ((lane & 3) == 0) {
                int r = mw * 32 + 16 * t + (lane >> 2);
                sred[r + 128 * nw]     = p0;
                sred[r + 8 + 128 * nw] = p1;
            }
        }
        __syncthreads();

        int tnn = tile + 2 * G;
        if (tnn < ETILES) {
            const char* sN = (const char*)(H + (size_t)n2 * 64);
            #pragma unroll
            for (int k = 0; k < 16; k++) CP16(rawDst + k * 16, sN + k * 16);
            CP_COMMIT();
            int tnnn = tile + 3 * G;
            if (tnnn < ETILES) n2 = __ldg(&idxp[tnnn * ET + el]);
        }

        // all 256 threads compute l; half write logits, half write probs
        {
            int ei = tid & 127;
            float l = sred[ei] + sred[ei + 128] + be2v;
            if (tid < 128) logits[e0 + ei] = l;
            else           probs[e0 + ei]  = 1.0f / (1.0f + __expf(-l));
        }
        b ^= 1;
    }
}

// ======================= launcher =======================
extern "C" void kernel_launch(void* const* d_in, const int* in_sizes, int n_in,
                              void* d_out, int out_size) {
    const float* x   = (const float*)d_in[0];
    const float* W1  = (const float*)d_in[1];
    const float* b1  = (const float*)d_in[2];
    const float* W2  = (const float*)d_in[3];
    const float* b2  = (const float*)d_in[4];
    const float* We1 = (const float*)d_in[5];
    const float* be1 = (const float*)d_in[6];
    const float* We2 = (const float*)d_in[7];
    const float* be2 = (const float*)d_in[8];
    const int*   ei  = (const int*)d_in[9];
    const int* src = ei;
    const int* dst = ei + NE;

    float* out    = (float*)d_out;
    float* H      = out;                 // [NN, 64]
    float* logits = out + NN * HID;      // [NE]
    float* probs  = logits + NE;         // [NE]

    void *yp, *h1p, *y2p, *zp;
    cudaGetSymbolAddress(&yp, g_y);
    cudaGetSymbolAddress(&h1p, g_h1);
    cudaGetSymbolAddress(&y2p, g_y2);
    cudaGetSymbolAddress(&zp, g_zeros);

    int sm128 = (64 * (INDIM + 4) + 20 * (2 * INDIM + 8)) * (int)sizeof(float);
    int sm64  = (64 * (HID + 4)   + 20 * (2 * HID + 8))   * (int)sizeof(float);
    cudaFuncSetAttribute(k_fk1,
                         cudaFuncAttributeMaxDynamicSharedMemorySize, sm128);
    cudaFuncSetAttribute(k_gemm<HID>,
                         cudaFuncAttributeMaxDynamicSharedMemorySize, sm64);

    // FK1: gemm layer1 (y = x@W1) + edge-count histogram (independent work)
    k_fk1<<<G1BLK + CNTBLK, GNT, sm128>>>(x, W1, dst, (float*)yp);
    // CSR scan (two launches, no inter-block protocol) + bucket
    k_scan1<<<NSCH, 1024>>>();
    k_scan23<<<NSCH, 1024>>>();
    k_bucket<<<(NE + 1023) / 1024, 1024>>>(src, dst);
    // layer 1 aggregation, layer 2
    k_aggr<<<NN / 16, 256>>>((const float*)yp, b1, (float*)h1p);
    k_gemm<HID><<<NN / GRT, GNT, sm64>>>((const float*)h1p, W2, (const float*)zp,
                                         (float*)y2p);
    k_aggr<<<NN / 16, 256>>>((const float*)y2p, b2, H);

    // fused edge MLP (interleaved-convert pipelined mma.sync, K=256)
    cudaFuncSetAttribute(k_edge, cudaFuncAttributeMaxDynamicSharedMemorySize,
                         SMEM_EDGE);
    k_edge<<<148, 256, SMEM_EDGE>>>(H, src, dst, We1, be1, We2, be2,
                                    logits, probs);
}

// round 16
// speedup vs baseline: 1.1816x; 1.1816x over previous
#include <cuda_runtime.h>
#include <cuda_fp16.h>
#include <cstdint>
#include <math.h>

#define NN 50000
#define NE 800000
#define INDIM 128
#define HID 64
#define NSCH 49   // ceil(NN/1024)

// ======================= device scratch =======================
__device__ int    g_deg[NN];          // static-zeroed; re-zeroed by k_scan23
__device__ int    g_row_start[NN + 1];
__device__ int    g_cursor[NN];
__device__ int    g_csr[NE];
__device__ float  g_invdeg[NN];
__device__ int    g_psum[64];
__device__ float  g_y[NN * HID];
__device__ float  g_h1[NN * HID];
__device__ float  g_y2[NN * HID];
__device__ __half g_Hh[NN * HID];     // fp16 copy of H for the edge gather
__device__ float  g_zeros[128];

// ======================= packed f32x2 helpers =======================
#define FMA2(c, a, b) asm("fma.rn.f32x2 %0, %1, %2, %3;" \
                          : "=l"(c) : "l"(a), "l"(b), "l"(c))
__device__ __forceinline__ unsigned long long pk(float lo, float hi) {
    unsigned long long r = (unsigned long long)__float_as_uint(lo);
    return r | ((unsigned long long)__float_as_uint(hi) << 32);
}

#define GRT 40
#define GNT 320
#define G1BLK (NN / GRT)      // 1250 gemm blocks in FK1
#define CNTBLK (NE / GNT)     // 2500 count blocks in FK1

// ============ FK1: fused [gemm layer1 (y = x@W1)] + [edge-count histogram] ============
__global__ void __launch_bounds__(GNT) k_fk1(const float* __restrict__ Z,
                                             const float* __restrict__ W,
                                             const int* __restrict__ dstE,
                                             float* __restrict__ out) {
    if (blockIdx.x >= G1BLK) {
        int e = (blockIdx.x - G1BLK) * GNT + threadIdx.x;
        if (e < NE) atomicAdd(&g_deg[dstE[e]], 1);
        return;
    }
    constexpr int K = INDIM;
    constexpr int KP = K + 4;
    constexpr int PSTR = 2 * K + 8;
    extern __shared__ float smg[];
    float* Ws  = smg;
    float* Zs2 = smg + 64 * KP;
    int tid = threadIdx.x;
    int j = tid % 64, rg = tid / 64;
    for (int idx = tid; idx < K * 64; idx += GNT) {
        int k = idx >> 6, c = idx & 63;
        Ws[c * KP + k] = W[idx];
    }
    int row0 = blockIdx.x * GRT;
    for (int idx = tid; idx < GRT * (K / 4); idx += GNT) {
        int r = idx / (K / 4), kq = idx % (K / 4);
        float4 v = reinterpret_cast<const float4*>(Z + (size_t)(row0 + r) * K)[kq];
        float* zb = Zs2 + (r >> 1) * PSTR + (r & 1) + 8 * kq;
        zb[0] = v.x; zb[2] = v.y; zb[4] = v.z; zb[6] = v.w;
    }
    __syncthreads();
    unsigned long long acc2[4];
    #pragma unroll
    for (int rp = 0; rp < 4; rp++) acc2[rp] = 0ull;
    const float4* w4 = reinterpret_cast<const float4*>(&Ws[j * KP]);
    #pragma unroll 8
    for (int k4 = 0; k4 < K / 4; k4++) {
        float4 w = w4[k4];
        unsigned long long w0 = pk(w.x, w.x), w1 = pk(w.y, w.y);
        unsigned long long w2 = pk(w.z, w.z), w3 = pk(w.w, w.w);
        #pragma unroll
        for (int rp = 0; rp < 4; rp++) {
            const ulonglong2* zp = reinterpret_cast<const ulonglong2*>(
                &Zs2[(rg * 4 + rp) * PSTR + 8 * k4]);
            ulonglong2 A = zp[0], B = zp[1];
            FMA2(acc2[rp], A.x, w0);
            FMA2(acc2[rp], A.y, w1);
            FMA2(acc2[rp], B.x, w2);
            FMA2(acc2[rp], B.y, w3);
        }
    }
    #pragma unroll
    for (int rp = 0; rp < 4; rp++) {
        float lo = __uint_as_float((unsigned)acc2[rp]);
        float hi = __uint_as_float((unsigned)(acc2[rp] >> 32));
        out[(size_t)(row0 + rg * 8 + 2 * rp) * 64 + j]     = lo;
        out[(size_t)(row0 + rg * 8 + 2 * rp + 1) * 64 + j] = hi;
    }
}

// ======================= CSR scan (two launches, proven path) =======================
__global__ void __launch_bounds__(1024) k_scan1() {
    __shared__ int wsum[32];
    int tid = threadIdx.x;
    int i = blockIdx.x * 1024 + tid;
    int v = (i < NN) ? g_deg[i] : 0;
    int xv = v;
    #pragma unroll
    for (int o = 1; o < 32; o <<= 1) {
        int y = __shfl_up_sync(0xffffffffu, xv, o);
        if ((tid & 31) >= o) xv += y;
    }
    if ((tid & 31) == 31) wsum[tid >> 5] = xv;
    __syncthreads();
    if (tid < 32) {
        int s = wsum[tid];
        #pragma unroll
        for (int o = 1; o < 32; o <<= 1) {
            int y = __shfl_up_sync(0xffffffffu, s, o);
            if (tid >= o) s += y;
        }
        wsum[tid] = s;
    }
    __syncthreads();
    int add = (tid >= 32) ? wsum[(tid >> 5) - 1] : 0;
    if (i < NN) g_row_start[i] = xv + add - v;
    if (tid == 0) g_psum[blockIdx.x] = wsum[31];
}

__global__ void __launch_bounds__(1024) k_scan23() {
    __shared__ int sexc[64];
    __shared__ int wtot;
    int tid = threadIdx.x;
    int v = 0, x = 0;
    if (tid < 64) {
        v = (tid < NSCH) ? g_psum[tid] : 0;
        x = v;
        #pragma unroll
        for (int o = 1; o < 32; o <<= 1) {
            int y = __shfl_up_sync(0xffffffffu, x, o);
            if ((tid & 31) >= o) x += y;
        }
        if (tid == 31) wtot = x;
    }
    __syncthreads();
    if (tid < 64) {
        int incl = x + ((tid >= 32) ? wtot : 0);
        sexc[tid] = incl - v;
        if (tid == NSCH - 1) g_row_start[NN] = incl;
    }
    __syncthreads();
    int off = sexc[blockIdx.x];
    int i = blockIdx.x * 1024 + tid;
    if (i < NN) {
        int rs = g_row_start[i] + off;
        g_row_start[i] = rs;
        g_cursor[i]    = rs;
        g_invdeg[i]    = 1.0f / fmaxf((float)g_deg[i], 1.0f);
        g_deg[i]       = 0;   // reset for next launch (deterministic)
    }
}

__global__ void __launch_bounds__(1024) k_bucket(const int* __restrict__ src,
                                                 const int* __restrict__ dst) {
    int e = blockIdx.x * 1024 + threadIdx.x;
    if (e < NE) {
        int d = dst[e];
        int p = atomicAdd(&g_cursor[d], 1);
        g_csr[p] = src[e];
    }
}

// ======= mean aggregation (fused bias + relu): out = relu(y + agg(y)/deg + b)
template <bool WRITE_H16>
__global__ void __launch_bounds__(256) k_aggrT(const float* __restrict__ y,
                                               const float* __restrict__ bias,
                                               float* __restrict__ out,
                                               __half* __restrict__ outh) {
    int node = blockIdx.x * 16 + (threadIdx.x >> 4);
    int c4 = (threadIdx.x & 15) * 4;
    int beg = g_row_start[node], end = g_row_start[node + 1];
    float4 acc = make_float4(0.f, 0.f, 0.f, 0.f);
    int e = beg;
    for (; e + 7 < end; e += 8) {
        int sI[8];
        #pragma unroll
        for (int u = 0; u < 8; u++) sI[u] = __ldg(&g_csr[e + u]);
        float4 v[8];
        #pragma unroll
        for (int u = 0; u < 8; u++)
            v[u] = *reinterpret_cast<const float4*>(y + (size_t)sI[u] * 64 + c4);
        #pragma unroll
        for (int u = 0; u < 8; u++) {
            acc.x += v[u].x; acc.y += v[u].y;
            acc.z += v[u].z; acc.w += v[u].w;
        }
    }
    for (; e < end; e++) {
        int s = __ldg(&g_csr[e]);
        float4 v = *reinterpret_cast<const float4*>(y + (size_t)s * 64 + c4);
        acc.x += v.x; acc.y += v.y; acc.z += v.z; acc.w += v.w;
    }
    float inv = g_invdeg[node];
    float4 self = *reinterpret_cast<const float4*>(y + (size_t)node * 64 + c4);
    float4 b = *reinterpret_cast<const float4*>(bias + c4);
    float4 r;
    r.x = fmaxf(self.x + acc.x * inv + b.x, 0.0f);
    r.y = fmaxf(self.y + acc.y * inv + b.y, 0.0f);
    r.z = fmaxf(self.z + acc.z * inv + b.z, 0.0f);
    r.w = fmaxf(self.w + acc.w * inv + b.w, 0.0f);
    *reinterpret_cast<float4*>(out + (size_t)node * 64 + c4) = r;
    if (WRITE_H16) {
        __half2 h0 = __floats2half2_rn(r.x, r.y);
        __half2 h1 = __floats2half2_rn(r.z, r.w);
        uint2 hh;
        hh.x = *reinterpret_cast<uint32_t*>(&h0);
        hh.y = *reinterpret_cast<uint32_t*>(&h1);
        *reinterpret_cast<uint2*>(outh + (size_t)node * 64 + c4) = hh;
    }
}

// ============ dense GEMM (layer 2) with packed f32x2 ============
template <int K>
__global__ void __launch_bounds__(GNT) k_gemm(const float* __restrict__ Z,
                                              const float* __restrict__ W,
                                              const float* __restrict__ bias,
                                              float* __restrict__ out) {
    constexpr int KP = K + 4;
    constexpr int PSTR = 2 * K + 8;
    extern __shared__ float smg[];
    float* Ws  = smg;
    float* Zs2 = smg + 64 * KP;
    int tid = threadIdx.x;
    int j = tid % 64, rg = tid / 64;
    for (int idx = tid; idx < K * 64; idx += GNT) {
        int k = idx >> 6, c = idx & 63;
        Ws[c * KP + k] = W[idx];
    }
    int row0 = blockIdx.x * GRT;
    for (int idx = tid; idx < GRT * (K / 4); idx += GNT) {
        int r = idx / (K / 4), kq = idx % (K / 4);
        float4 v = reinterpret_cast<const float4*>(Z + (size_t)(row0 + r) * K)[kq];
        float* zb = Zs2 + (r >> 1) * PSTR + (r & 1) + 8 * kq;
        zb[0] = v.x; zb[2] = v.y; zb[4] = v.z; zb[6] = v.w;
    }
    __syncthreads();
    float bj = bias[j];
    unsigned long long acc2[4];
    #pragma unroll
    for (int rp = 0; rp < 4; rp++) acc2[rp] = pk(bj, bj);
    const float4* w4 = reinterpret_cast<const float4*>(&Ws[j * KP]);
    #pragma unroll 8
    for (int k4 = 0; k4 < K / 4; k4++) {
        float4 w = w4[k4];
        unsigned long long w0 = pk(w.x, w.x), w1 = pk(w.y, w.y);
        unsigned long long w2 = pk(w.z, w.z), w3 = pk(w.w, w.w);
        #pragma unroll
        for (int rp = 0; rp < 4; rp++) {
            const ulonglong2* zp = reinterpret_cast<const ulonglong2*>(
                &Zs2[(rg * 4 + rp) * PSTR + 8 * k4]);
            ulonglong2 A = zp[0], B = zp[1];
            FMA2(acc2[rp], A.x, w0);
            FMA2(acc2[rp], A.y, w1);
            FMA2(acc2[rp], B.x, w2);
            FMA2(acc2[rp], B.y, w3);
        }
    }
    #pragma unroll
    for (int rp = 0; rp < 4; rp++) {
        float lo = __uint_as_float((unsigned)acc2[rp]);
        float hi = __uint_as_float((unsigned)(acc2[rp] >> 32));
        out[(size_t)(row0 + rg * 8 + 2 * rp) * 64 + j]     = lo;
        out[(size_t)(row0 + rg * 8 + 2 * rp + 1) * 64 + j] = hi;
    }
}

// ======================= fused edge MLP: fp16-H gather, interleaved pipeline ======
// Gather reads the fp16 copy of H (128B/row, half the fp32 traffic).
#define ET 128
#define ETILES (NE / ET)         // 6250
#define ROWB 528                 // A row: 264 halfs (8-half pad)
#define RAWB 304                 // raw fp16: hs 128B @0, hd 128B @160 (bank-safe)
#define OFF_A0 1024
#define OFF_A1 (OFF_A0 + 128 * ROWB)         // 68608
#define OFF_RAW (OFF_A1 + 128 * ROWB)        // 136192
#define SMEM_EDGE (OFF_RAW + 128 * RAWB)     // 175104

__device__ __forceinline__ uint32_t smem_u32(const void* p) {
    uint32_t a;
    asm("{ .reg .u64 t; cvta.to.shared.u64 t, %1; cvt.u32.u64 %0, t; }"
        : "=r"(a) : "l"(p));
    return a;
}

#define CP16(d, s) asm volatile("cp.async.cg.shared.global [%0], [%1], 16;" \
                                :: "r"(d), "l"(s))
#define CP_COMMIT() asm volatile("cp.async.commit_group;" ::: "memory")
#define CP_WAIT0()  asm volatile("cp.async.wait_group 0;" ::: "memory")

#define LDSM4(r, addr)                                                         \
    asm volatile("ldmatrix.sync.aligned.m8n8.x4.shared.b16 {%0,%1,%2,%3}, [%4];" \
                 : "=r"((r)[0]), "=r"((r)[1]), "=r"((r)[2]), "=r"((r)[3])      \
                 : "r"(addr))

#define MMA16816(d, a, b)                                                      \
    asm volatile("mma.sync.aligned.m16n8k16.row.col.f32.f16.f16.f32 "          \
                 "{%0,%1,%2,%3},{%4,%5,%6,%7},{%8,%9},{%0,%1,%2,%3};"          \
                 : "+f"((d)[0]), "+f"((d)[1]), "+f"((d)[2]), "+f"((d)[3])      \
                 : "r"((a)[0]), "r"((a)[1]), "r"((a)[2]), "r"((a)[3]),         \
                   "r"((b)[0]), "r"((b)[1]))

// convert chunk c: fp16 hs,hd slices -> copy + compute p,q (fp16)
__device__ __forceinline__ void conv_chunk(const char* rawB, char* rA,
                                           int el, int q, int c) {
    uint4 hs4 = *reinterpret_cast<const uint4*>(rawB + el * RAWB + q * 64 + c * 16);
    uint4 hd4 = *reinterpret_cast<const uint4*>(rawB + el * RAWB + 160 + q * 64 + c * 16);
    const __half2* hsp = reinterpret_cast<const __half2*>(&hs4);
    const __half2* hdp = reinterpret_cast<const __half2*>(&hd4);
    uint32_t pw[4], qw[4];
    #pragma unroll
    for (int i = 0; i < 4; i++) {
        float2 a = __half22float2(hsp[i]);
        float2 b = __half22float2(hdp[i]);
        __half2 p2 = __floats2half2_rn(a.x * b.x, a.y * b.y);
        __half2 q2 = __floats2half2_rn(fabsf(a.x - b.x), fabsf(a.y - b.y));
        pw[i] = *reinterpret_cast<uint32_t*>(&p2);
        qw[i] = *reinterpret_cast<uint32_t*>(&q2);
    }
    int kb = (q * 32 + 8 * c) * 2;
    *reinterpret_cast<uint4*>(rA + kb)       = hs4;
    *reinterpret_cast<uint4*>(rA + kb + 128) = hd4;
    *reinterpret_cast<uint4*>(rA + kb + 256) = make_uint4(pw[0], pw[1], pw[2], pw[3]);
    *reinterpret_cast<uint4*>(rA + kb + 384) = make_uint4(qw[0], qw[1], qw[2], qw[3]);
}

__global__ void __launch_bounds__(256, 1) k_edge(
    const __half* __restrict__ Hh, const int* __restrict__ src,
    const int* __restrict__ dst, const float* __restrict__ We1,
    const float* __restrict__ be1, const float* __restrict__ We2,
    const float* __restrict__ be2,
    float* __restrict__ logits, float* __restrict__ probs) {
    extern __shared__ char sm[];
    float* sred = reinterpret_cast<float*>(sm);
    char* A0B  = sm + OFF_A0;
    char* A1B  = sm + OFF_A1;
    char* rawB = sm + OFF_RAW;

    int tid = threadIdx.x, lane = tid & 31, wid = tid >> 5;
    int mw = wid & 3, nw = wid >> 2;

    uint32_t bF[16][4][2];
    #pragma unroll
    for (int s = 0; s < 16; s++)
        #pragma unroll
        for (int j = 0; j < 4; j++)
            #pragma unroll
            for (int r = 0; r < 2; r++) {
                int k = s * 16 + 2 * (lane & 3) + r * 8;
                int n = nw * 32 + j * 8 + (lane >> 2);
                __half2 h = __floats2half2_rn(__ldg(&We1[k * 64 + n]),
                                              __ldg(&We1[(k + 1) * 64 + n]));
                bF[s][j][r] = *reinterpret_cast<uint32_t*>(&h);
            }
    float bb[4][2], ww[4][2];
    #pragma unroll
    for (int j = 0; j < 4; j++)
        #pragma unroll
        for (int c = 0; c < 2; c++) {
            int nc = nw * 32 + j * 8 + 2 * (lane & 3) + c;
            bb[j][c] = __ldg(&be1[nc]);
            ww[j][c] = __ldg(&We2[nc]);
        }
    float be2v = be2[0];

    int el = tid >> 1, q = tid & 1;
    const int* idxp = q ? dst : src;   // q=0: hs row, q=1: hd row
    uint32_t rawDst = smem_u32(rawB + el * RAWB + q * 160);
    uint32_t Aaddr[2] = {smem_u32(A0B), smem_u32(A1B)};
    char* Abuf[2] = {A0B, A1B};
    uint32_t mrow = (uint32_t)(mw * 32 + (lane & 15)) * ROWB + (lane >> 4) * 16;
    int G = gridDim.x;

    int tile0 = blockIdx.x;
    {
        int n0 = __ldg(&idxp[tile0 * ET + el]);
        const char* s0 = (const char*)(Hh + (size_t)n0 * 64);
        #pragma unroll
        for (int k = 0; k < 8; k++) CP16(rawDst + k * 16, s0 + k * 16);
        CP_COMMIT();
    }
    int t1 = tile0 + G;
    int n1 = (t1 < ETILES) ? __ldg(&idxp[t1 * ET + el]) : 0;
    CP_WAIT0();
    __syncthreads();
    {
        char* rA = A0B + el * ROWB;
        #pragma unroll
        for (int c = 0; c < 4; c++) conv_chunk(rawB, rA, el, q, c);
    }
    __syncthreads();
    if (t1 < ETILES) {
        const char* sN = (const char*)(Hh + (size_t)n1 * 64);
        #pragma unroll
        for (int k = 0; k < 8; k++) CP16(rawDst + k * 16, sN + k * 16);
        CP_COMMIT();
    }
    int t2 = t1 + G;
    int n2 = (t2 < ETILES) ? __ldg(&idxp[t2 * ET + el]) : 0;

    int b = 0;
    for (int tile = tile0; tile < ETILES; tile += G) {
        int e0 = tile * ET;
        int hasNext = (tile + G < ETILES);
        CP_WAIT0();
        __syncthreads();

        float dacc[2][4][4];
        #pragma unroll
        for (int t = 0; t < 2; t++)
            #pragma unroll
            for (int j = 0; j < 4; j++)
                #pragma unroll
                for (int r = 0; r < 4; r++) dacc[t][j][r] = 0.0f;

        uint32_t base = Aaddr[b] + mrow;
        char* rAother = Abuf[b ^ 1] + el * ROWB;
        #pragma unroll
        for (int s = 0; s < 16; s++) {
            uint32_t a0[4], a1[4];
            LDSM4(a0, base + s * 32);
            LDSM4(a1, base + 16 * ROWB + s * 32);
            #pragma unroll
            for (int j = 0; j < 4; j++) {
                MMA16816(dacc[0][j], a0, bF[s][j]);
                MMA16816(dacc[1][j], a1, bF[s][j]);
            }
            if ((s & 3) == 0 && hasNext)
                conv_chunk(rawB, rAother, el, q, s >> 2);
        }

        #pragma unroll
        for (int t = 0; t < 2; t++) {
            float p0 = 0.0f, p1 = 0.0f;
            #pragma unroll
            for (int j = 0; j < 4; j++) {
                p0 += fmaxf(dacc[t][j][0] + bb[j][0], 0.0f) * ww[j][0];
                p0 += fmaxf(dacc[t][j][1] + bb[j][1], 0.0f) * ww[j][1];
                p1 += fmaxf(dacc[t][j][2] + bb[j][0], 0.0f) * ww[j][0];
                p1 += fmaxf(dacc[t][j][3] + bb[j][1], 0.0f) * ww[j][1];
            }
            p0 += __shfl_xor_sync(0xffffffffu, p0, 1);
            p0 += __shfl_xor_sync(0xffffffffu, p0, 2);
            p1 += __shfl_xor_sync(0xffffffffu, p1, 1);
            p1 += __shfl_xor_sync(0xffffffffu, p1, 2);
            if ((lane & 3) == 0) {
                int r = mw * 32 + 16 * t + (lane >> 2);
                sred[r + 128 * nw]     = p0;
                sred[r + 8 + 128 * nw] = p1;
            }
        }
        __syncthreads();

        int tnn = tile + 2 * G;
        if (tnn < ETILES) {
            const char* sN = (const char*)(Hh + (size_t)n2 * 64);
            #pragma unroll
            for (int k = 0; k < 8; k++) CP16(rawDst + k * 16, sN + k * 16);
            CP_COMMIT();
            int tnnn = tile + 3 * G;
            if (tnnn < ETILES) n2 = __ldg(&idxp[tnnn * ET + el]);
        }

        {
            int ei = tid & 127;
            float l = sred[ei] + sred[ei + 128] + be2v;
            if (tid < 128) logits[e0 + ei] = l;
            else           probs[e0 + ei]  = 1.0f / (1.0f + __expf(-l));
        }
        b ^= 1;
    }
}

// ======================= launcher =======================
extern "C" void kernel_launch(void* const* d_in, const int* in_sizes, int n_in,
                              void* d_out, int out_size) {
    const float* x   = (const float*)d_in[0];
    const float* W1  = (const float*)d_in[1];
    const float* b1  = (const float*)d_in[2];
    const float* W2  = (const float*)d_in[3];
    const float* b2  = (const float*)d_in[4];
    const float* We1 = (const float*)d_in[5];
    const float* be1 = (const float*)d_in[6];
    const float* We2 = (const float*)d_in[7];
    const float* be2 = (const float*)d_in[8];
    const int*   ei  = (const int*)d_in[9];
    const int* src = ei;
    const int* dst = ei + NE;

    float* out    = (float*)d_out;
    float* H      = out;                 // [NN, 64]
    float* logits = out + NN * HID;      // [NE]
    float* probs  = logits + NE;         // [NE]

    void *yp, *h1p, *y2p, *zp, *hhp;
    cudaGetSymbolAddress(&yp, g_y);
    cudaGetSymbolAddress(&h1p, g_h1);
    cudaGetSymbolAddress(&y2p, g_y2);
    cudaGetSymbolAddress(&zp, g_zeros);
    cudaGetSymbolAddress(&hhp, g_Hh);

    int sm128 = (64 * (INDIM + 4) + 20 * (2 * INDIM + 8)) * (int)sizeof(float);
    int sm64  = (64 * (HID + 4)   + 20 * (2 * HID + 8))   * (int)sizeof(float);
    cudaFuncSetAttribute(k_fk1,
                         cudaFuncAttributeMaxDynamicSharedMemorySize, sm128);
    cudaFuncSetAttribute(k_gemm<HID>,
                         cudaFuncAttributeMaxDynamicSharedMemorySize, sm64);

    // FK1: gemm layer1 (y = x@W1) + edge-count histogram (independent work)
    k_fk1<<<G1BLK + CNTBLK, GNT, sm128>>>(x, W1, dst, (float*)yp);
    // CSR scan + bucket
    k_scan1<<<NSCH, 1024>>>();
    k_scan23<<<NSCH, 1024>>>();
    k_bucket<<<(NE + 1023) / 1024, 1024>>>(src, dst);
    // layer 1 aggregation, layer 2
    k_aggrT<false><<<NN / 16, 256>>>((const float*)yp, b1, (float*)h1p, nullptr);
    k_gemm<HID><<<NN / GRT, GNT, sm64>>>((const float*)h1p, W2, (const float*)zp,
                                         (float*)y2p);
    // layer-2 aggregation writes H (fp32, d_out) + fp16 copy for edge gather
    k_aggrT<true><<<NN / 16, 256>>>((const float*)y2p, b2, H, (__half*)hhp);

    // fused edge MLP (fp16-H gather, interleaved pipelined mma.sync, K=256)
    cudaFuncSetAttribute(k_edge, cudaFuncAttributeMaxDynamicSharedMemorySize,
                         SMEM_EDGE);
    k_edge<<<148, 256, SMEM_EDGE>>>((const __half*)hhp, src, dst, We1, be1,
                                    We2, be2, logits, probs);
}

// round 17
// speedup vs baseline: 1.1970x; 1.0130x over previous
#include <cuda_runtime.h>
#include <cuda_fp16.h>
#include <cstdint>
#include <math.h>

#define NN 50000
#define NE 800000
#define INDIM 128
#define HID 64
#define NSCH 49   // ceil(NN/1024)

// ======================= device scratch =======================
__device__ int    g_deg[NN];          // static-zeroed; re-zeroed by k_scan23
__device__ int    g_row_start[NN + 1];
__device__ int    g_cursor[NN];
__device__ int    g_csr[NE];
__device__ float  g_invdeg[NN];
__device__ int    g_psum[64];
__device__ float  g_y[NN * HID];
__device__ float  g_h1[NN * HID];
__device__ float  g_y2[NN * HID];
__device__ __half g_y16[NN * HID];    // fp16 copy of gemm output for agg gather
__device__ __half g_Hh[NN * HID];     // fp16 copy of H for the edge gather
__device__ float  g_zeros[128];

// ======================= packed f32x2 helpers =======================
#define FMA2(c, a, b) asm("fma.rn.f32x2 %0, %1, %2, %3;" \
                          : "=l"(c) : "l"(a), "l"(b), "l"(c))
__device__ __forceinline__ unsigned long long pk(float lo, float hi) {
    unsigned long long r = (unsigned long long)__float_as_uint(lo);
    return r | ((unsigned long long)__float_as_uint(hi) << 32);
}

#define GRT 40
#define GNT 320
#define G1BLK (NN / GRT)      // 1250 gemm blocks in FK1
#define CNTBLK (NE / GNT)     // 2500 count blocks in FK1

// ============ FK1: fused [gemm layer1 (y = x@W1, fp32+fp16)] + [edge-count] ============
__global__ void __launch_bounds__(GNT) k_fk1(const float* __restrict__ Z,
                                             const float* __restrict__ W,
                                             const int* __restrict__ dstE,
                                             float* __restrict__ out,
                                             __half* __restrict__ outh) {
    if (blockIdx.x >= G1BLK) {
        int e = (blockIdx.x - G1BLK) * GNT + threadIdx.x;
        if (e < NE) atomicAdd(&g_deg[dstE[e]], 1);
        return;
    }
    constexpr int K = INDIM;
    constexpr int KP = K + 4;
    constexpr int PSTR = 2 * K + 8;
    extern __shared__ float smg[];
    float* Ws  = smg;
    float* Zs2 = smg + 64 * KP;
    int tid = threadIdx.x;
    int j = tid % 64, rg = tid / 64;
    for (int idx = tid; idx < K * 64; idx += GNT) {
        int k = idx >> 6, c = idx & 63;
        Ws[c * KP + k] = W[idx];
    }
    int row0 = blockIdx.x * GRT;
    for (int idx = tid; idx < GRT * (K / 4); idx += GNT) {
        int r = idx / (K / 4), kq = idx % (K / 4);
        float4 v = reinterpret_cast<const float4*>(Z + (size_t)(row0 + r) * K)[kq];
        float* zb = Zs2 + (r >> 1) * PSTR + (r & 1) + 8 * kq;
        zb[0] = v.x; zb[2] = v.y; zb[4] = v.z; zb[6] = v.w;
    }
    __syncthreads();
    unsigned long long acc2[4];
    #pragma unroll
    for (int rp = 0; rp < 4; rp++) acc2[rp] = 0ull;
    const float4* w4 = reinterpret_cast<const float4*>(&Ws[j * KP]);
    #pragma unroll 8
    for (int k4 = 0; k4 < K / 4; k4++) {
        float4 w = w4[k4];
        unsigned long long w0 = pk(w.x, w.x), w1 = pk(w.y, w.y);
        unsigned long long w2 = pk(w.z, w.z), w3 = pk(w.w, w.w);
        #pragma unroll
        for (int rp = 0; rp < 4; rp++) {
            const ulonglong2* zp = reinterpret_cast<const ulonglong2*>(
                &Zs2[(rg * 4 + rp) * PSTR + 8 * k4]);
            ulonglong2 A = zp[0], B = zp[1];
            FMA2(acc2[rp], A.x, w0);
            FMA2(acc2[rp], A.y, w1);
            FMA2(acc2[rp], B.x, w2);
            FMA2(acc2[rp], B.y, w3);
        }
    }
    #pragma unroll
    for (int rp = 0; rp < 4; rp++) {
        float lo = __uint_as_float((unsigned)acc2[rp]);
        float hi = __uint_as_float((unsigned)(acc2[rp] >> 32));
        size_t r0 = (size_t)(row0 + rg * 8 + 2 * rp);
        out[r0 * 64 + j]       = lo;
        out[(r0 + 1) * 64 + j] = hi;
        outh[r0 * 64 + j]       = __float2half(lo);
        outh[(r0 + 1) * 64 + j] = __float2half(hi);
    }
}

// ======================= CSR scan (two launches, proven path) =======================
__global__ void __launch_bounds__(1024) k_scan1() {
    __shared__ int wsum[32];
    int tid = threadIdx.x;
    int i = blockIdx.x * 1024 + tid;
    int v = (i < NN) ? g_deg[i] : 0;
    int xv = v;
    #pragma unroll
    for (int o = 1; o < 32; o <<= 1) {
        int y = __shfl_up_sync(0xffffffffu, xv, o);
        if ((tid & 31) >= o) xv += y;
    }
    if ((tid & 31) == 31) wsum[tid >> 5] = xv;
    __syncthreads();
    if (tid < 32) {
        int s = wsum[tid];
        #pragma unroll
        for (int o = 1; o < 32; o <<= 1) {
            int y = __shfl_up_sync(0xffffffffu, s, o);
            if (tid >= o) s += y;
        }
        wsum[tid] = s;
    }
    __syncthreads();
    int add = (tid >= 32) ? wsum[(tid >> 5) - 1] : 0;
    if (i < NN) g_row_start[i] = xv + add - v;
    if (tid == 0) g_psum[blockIdx.x] = wsum[31];
}

__global__ void __launch_bounds__(1024) k_scan23() {
    __shared__ int sexc[64];
    __shared__ int wtot;
    int tid = threadIdx.x;
    int v = 0, x = 0;
    if (tid < 64) {
        v = (tid < NSCH) ? g_psum[tid] : 0;
        x = v;
        #pragma unroll
        for (int o = 1; o < 32; o <<= 1) {
            int y = __shfl_up_sync(0xffffffffu, x, o);
            if ((tid & 31) >= o) x += y;
        }
        if (tid == 31) wtot = x;
    }
    __syncthreads();
    if (tid < 64) {
        int incl = x + ((tid >= 32) ? wtot : 0);
        sexc[tid] = incl - v;
        if (tid == NSCH - 1) g_row_start[NN] = incl;
    }
    __syncthreads();
    int off = sexc[blockIdx.x];
    int i = blockIdx.x * 1024 + tid;
    if (i < NN) {
        int rs = g_row_start[i] + off;
        g_row_start[i] = rs;
        g_cursor[i]    = rs;
        g_invdeg[i]    = 1.0f / fmaxf((float)g_deg[i], 1.0f);
        g_deg[i]       = 0;   // reset for next launch (deterministic)
    }
}

__global__ void __launch_bounds__(1024) k_bucket(const int* __restrict__ src,
                                                 const int* __restrict__ dst) {
    int e = blockIdx.x * 1024 + threadIdx.x;
    if (e < NE) {
        int d = dst[e];
        int p = atomicAdd(&g_cursor[d], 1);
        g_csr[p] = src[e];
    }
}

// ======= mean aggregation: gathers NEIGHBORS from fp16 copy; self/out fp32
template <bool WRITE_H16>
__global__ void __launch_bounds__(256) k_aggrT(const float* __restrict__ y,
                                               const __half* __restrict__ y16,
                                               const float* __restrict__ bias,
                                               float* __restrict__ out,
                                               __half* __restrict__ outh) {
    int node = blockIdx.x * 16 + (threadIdx.x >> 4);
    int c4 = (threadIdx.x & 15) * 4;
    int beg = g_row_start[node], end = g_row_start[node + 1];
    float4 acc = make_float4(0.f, 0.f, 0.f, 0.f);
    int e = beg;
    for (; e + 7 < end; e += 8) {
        int sI[8];
        #pragma unroll
        for (int u = 0; u < 8; u++) sI[u] = __ldg(&g_csr[e + u]);
        uint2 hv[8];
        #pragma unroll
        for (int u = 0; u < 8; u++)
            hv[u] = *reinterpret_cast<const uint2*>(y16 + (size_t)sI[u] * 64 + c4);
        #pragma unroll
        for (int u = 0; u < 8; u++) {
            float2 f0 = __half22float2(*reinterpret_cast<__half2*>(&hv[u].x));
            float2 f1 = __half22float2(*reinterpret_cast<__half2*>(&hv[u].y));
            acc.x += f0.x; acc.y += f0.y; acc.z += f1.x; acc.w += f1.y;
        }
    }
    for (; e < end; e++) {
        int s = __ldg(&g_csr[e]);
        uint2 hv = *reinterpret_cast<const uint2*>(y16 + (size_t)s * 64 + c4);
        float2 f0 = __half22float2(*reinterpret_cast<__half2*>(&hv.x));
        float2 f1 = __half22float2(*reinterpret_cast<__half2*>(&hv.y));
        acc.x += f0.x; acc.y += f0.y; acc.z += f1.x; acc.w += f1.y;
    }
    float inv = g_invdeg[node];
    float4 self = *reinterpret_cast<const float4*>(y + (size_t)node * 64 + c4);
    float4 b = *reinterpret_cast<const float4*>(bias + c4);
    float4 r;
    r.x = fmaxf(self.x + acc.x * inv + b.x, 0.0f);
    r.y = fmaxf(self.y + acc.y * inv + b.y, 0.0f);
    r.z = fmaxf(self.z + acc.z * inv + b.z, 0.0f);
    r.w = fmaxf(self.w + acc.w * inv + b.w, 0.0f);
    *reinterpret_cast<float4*>(out + (size_t)node * 64 + c4) = r;
    if (WRITE_H16) {
        __half2 h0 = __floats2half2_rn(r.x, r.y);
        __half2 h1 = __floats2half2_rn(r.z, r.w);
        uint2 hh;
        hh.x = *reinterpret_cast<uint32_t*>(&h0);
        hh.y = *reinterpret_cast<uint32_t*>(&h1);
        *reinterpret_cast<uint2*>(outh + (size_t)node * 64 + c4) = hh;
    }
}

// ============ dense GEMM (layer 2), fp32 + fp16 outputs ============
template <int K>
__global__ void __launch_bounds__(GNT) k_gemm(const float* __restrict__ Z,
                                              const float* __restrict__ W,
                                              const float* __restrict__ bias,
                                              float* __restrict__ out,
                                              __half* __restrict__ outh) {
    constexpr int KP = K + 4;
    constexpr int PSTR = 2 * K + 8;
    extern __shared__ float smg[];
    float* Ws  = smg;
    float* Zs2 = smg + 64 * KP;
    int tid = threadIdx.x;
    int j = tid % 64, rg = tid / 64;
    for (int idx = tid; idx < K * 64; idx += GNT) {
        int k = idx >> 6, c = idx & 63;
        Ws[c * KP + k] = W[idx];
    }
    int row0 = blockIdx.x * GRT;
    for (int idx = tid; idx < GRT * (K / 4); idx += GNT) {
        int r = idx / (K / 4), kq = idx % (K / 4);
        float4 v = reinterpret_cast<const float4*>(Z + (size_t)(row0 + r) * K)[kq];
        float* zb = Zs2 + (r >> 1) * PSTR + (r & 1) + 8 * kq;
        zb[0] = v.x; zb[2] = v.y; zb[4] = v.z; zb[6] = v.w;
    }
    __syncthreads();
    float bj = bias[j];
    unsigned long long acc2[4];
    #pragma unroll
    for (int rp = 0; rp < 4; rp++) acc2[rp] = pk(bj, bj);
    const float4* w4 = reinterpret_cast<const float4*>(&Ws[j * KP]);
    #pragma unroll 8
    for (int k4 = 0; k4 < K / 4; k4++) {
        float4 w = w4[k4];
        unsigned long long w0 = pk(w.x, w.x), w1 = pk(w.y, w.y);
        unsigned long long w2 = pk(w.z, w.z), w3 = pk(w.w, w.w);
        #pragma unroll
        for (int rp = 0; rp < 4; rp++) {
            const ulonglong2* zp = reinterpret_cast<const ulonglong2*>(
                &Zs2[(rg * 4 + rp) * PSTR + 8 * k4]);
            ulonglong2 A = zp[0], B = zp[1];
            FMA2(acc2[rp], A.x, w0);
            FMA2(acc2[rp], A.y, w1);
            FMA2(acc2[rp], B.x, w2);
            FMA2(acc2[rp], B.y, w3);
        }
    }
    #pragma unroll
    for (int rp = 0; rp < 4; rp++) {
        float lo = __uint_as_float((unsigned)acc2[rp]);
        float hi = __uint_as_float((unsigned)(acc2[rp] >> 32));
        size_t r0 = (size_t)(row0 + rg * 8 + 2 * rp);
        out[r0 * 64 + j]       = lo;
        out[(r0 + 1) * 64 + j] = hi;
        outh[r0 * 64 + j]       = __float2half(lo);
        outh[(r0 + 1) * 64 + j] = __float2half(hi);
    }
}

// ======================= fused edge MLP: fp16-H gather, interleaved pipeline ======
#define ET 128
#define ETILES (NE / ET)         // 6250
#define ROWB 528                 // A row: 264 halfs (8-half pad)
#define RAWB 304                 // raw fp16: hs 128B @0, hd 128B @160
#define OFF_A0 1024
#define OFF_A1 (OFF_A0 + 128 * ROWB)         // 68608
#define OFF_RAW (OFF_A1 + 128 * ROWB)        // 136192
#define SMEM_EDGE (OFF_RAW + 128 * RAWB)     // 175104

__device__ __forceinline__ uint32_t smem_u32(const void* p) {
    uint32_t a;
    asm("{ .reg .u64 t; cvta.to.shared.u64 t, %1; cvt.u32.u64 %0, t; }"
        : "=r"(a) : "l"(p));
    return a;
}

#define CP16(d, s) asm volatile("cp.async.cg.shared.global [%0], [%1], 16;" \
                                :: "r"(d), "l"(s))
#define CP_COMMIT() asm volatile("cp.async.commit_group;" ::: "memory")
#define CP_WAIT0()  asm volatile("cp.async.wait_group 0;" ::: "memory")

#define LDSM4(r, addr)                                                         \
    asm volatile("ldmatrix.sync.aligned.m8n8.x4.shared.b16 {%0,%1,%2,%3}, [%4];" \
                 : "=r"((r)[0]), "=r"((r)[1]), "=r"((r)[2]), "=r"((r)[3])      \
                 : "r"(addr))

#define MMA16816(d, a, b)                                                      \
    asm volatile("mma.sync.aligned.m16n8k16.row.col.f32.f16.f16.f32 "          \
                 "{%0,%1,%2,%3},{%4,%5,%6,%7},{%8,%9},{%0,%1,%2,%3};"          \
                 : "+f"((d)[0]), "+f"((d)[1]), "+f"((d)[2]), "+f"((d)[3])      \
                 : "r"((a)[0]), "r"((a)[1]), "r"((a)[2]), "r"((a)[3]),         \
                   "r"((b)[0]), "r"((b)[1]))

// convert chunk c: fp16 hs,hd slices -> copy + compute p,q (fp16)
__device__ __forceinline__ void conv_chunk(const char* rawB, char* rA,
                                           int el, int q, int c) {
    uint4 hs4 = *reinterpret_cast<const uint4*>(rawB + el * RAWB + q * 64 + c * 16);
    uint4 hd4 = *reinterpret_cast<const uint4*>(rawB + el * RAWB + 160 + q * 64 + c * 16);
    const __half2* hsp = reinterpret_cast<const __half2*>(&hs4);
    const __half2* hdp = reinterpret_cast<const __half2*>(&hd4);
    uint32_t pw[4], qw[4];
    #pragma unroll
    for (int i = 0; i < 4; i++) {
        float2 a = __half22float2(hsp[i]);
        float2 b = __half22float2(hdp[i]);
        __half2 p2 = __floats2half2_rn(a.x * b.x, a.y * b.y);
        __half2 q2 = __floats2half2_rn(fabsf(a.x - b.x), fabsf(a.y - b.y));
        pw[i] = *reinterpret_cast<uint32_t*>(&p2);
        qw[i] = *reinterpret_cast<uint32_t*>(&q2);
    }
    int kb = (q * 32 + 8 * c) * 2;
    *reinterpret_cast<uint4*>(rA + kb)       = hs4;
    *reinterpret_cast<uint4*>(rA + kb + 128) = hd4;
    *reinterpret_cast<uint4*>(rA + kb + 256) = make_uint4(pw[0], pw[1], pw[2], pw[3]);
    *reinterpret_cast<uint4*>(rA + kb + 384) = make_uint4(qw[0], qw[1], qw[2], qw[3]);
}

__global__ void __launch_bounds__(256, 1) k_edge(
    const __half* __restrict__ Hh, const int* __restrict__ src,
    const int* __restrict__ dst, const float* __restrict__ We1,
    const float* __restrict__ be1, const float* __restrict__ We2,
    const float* __restrict__ be2,
    float* __restrict__ logits, float* __restrict__ probs) {
    extern __shared__ char sm[];
    float* sred = reinterpret_cast<float*>(sm);
    char* A0B  = sm + OFF_A0;
    char* A1B  = sm + OFF_A1;
    char* rawB = sm + OFF_RAW;

    int tid = threadIdx.x, lane = tid & 31, wid = tid >> 5;
    int mw = wid & 3, nw = wid >> 2;

    uint32_t bF[16][4][2];
    #pragma unroll
    for (int s = 0; s < 16; s++)
        #pragma unroll
        for (int j = 0; j < 4; j++)
            #pragma unroll
            for (int r = 0; r < 2; r++) {
                int k = s * 16 + 2 * (lane & 3) + r * 8;
                int n = nw * 32 + j * 8 + (lane >> 2);
                __half2 h = __floats2half2_rn(__ldg(&We1[k * 64 + n]),
                                              __ldg(&We1[(k + 1) * 64 + n]));
                bF[s][j][r] = *reinterpret_cast<uint32_t*>(&h);
            }
    float bb[4][2], ww[4][2];
    #pragma unroll
    for (int j = 0; j < 4; j++)
        #pragma unroll
        for (int c = 0; c < 2; c++) {
            int nc = nw * 32 + j * 8 + 2 * (lane & 3) + c;
            bb[j][c] = __ldg(&be1[nc]);
            ww[j][c] = __ldg(&We2[nc]);
        }
    float be2v = be2[0];

    int el = tid >> 1, q = tid & 1;
    const int* idxp = q ? dst : src;
    uint32_t rawDst = smem_u32(rawB + el * RAWB + q * 160);
    uint32_t Aaddr[2] = {smem_u32(A0B), smem_u32(A1B)};
    char* Abuf[2] = {A0B, A1B};
    uint32_t mrow = (uint32_t)(mw * 32 + (lane & 15)) * ROWB + (lane >> 4) * 16;
    int G = gridDim.x;

    int tile0 = blockIdx.x;
    {
        int n0 = __ldg(&idxp[tile0 * ET + el]);
        const char* s0 = (const char*)(Hh + (size_t)n0 * 64);
        #pragma unroll
        for (int k = 0; k < 8; k++) CP16(rawDst + k * 16, s0 + k * 16);
        CP_COMMIT();
    }
    int t1 = tile0 + G;
    int n1 = (t1 < ETILES) ? __ldg(&idxp[t1 * ET + el]) : 0;
    CP_WAIT0();
    __syncthreads();
    {
        char* rA = A0B + el * ROWB;
        #pragma unroll
        for (int c = 0; c < 4; c++) conv_chunk(rawB, rA, el, q, c);
    }
    __syncthreads();
    if (t1 < ETILES) {
        const char* sN = (const char*)(Hh + (size_t)n1 * 64);
        #pragma unroll
        for (int k = 0; k < 8; k++) CP16(rawDst + k * 16, sN + k * 16);
        CP_COMMIT();
    }
    int t2 = t1 + G;
    int n2 = (t2 < ETILES) ? __ldg(&idxp[t2 * ET + el]) : 0;

    int b = 0;
    for (int tile = tile0; tile < ETILES; tile += G) {
        int e0 = tile * ET;
        int hasNext = (tile + G < ETILES);
        CP_WAIT0();
        __syncthreads();

        float dacc[2][4][4];
        #pragma unroll
        for (int t = 0; t < 2; t++)
            #pragma unroll
            for (int j = 0; j < 4; j++)
                #pragma unroll
                for (int r = 0; r < 4; r++) dacc[t][j][r] = 0.0f;

        uint32_t base = Aaddr[b] + mrow;
        char* rAother = Abuf[b ^ 1] + el * ROWB;
        #pragma unroll
        for (int s = 0; s < 16; s++) {
            uint32_t a0[4], a1[4];
            LDSM4(a0, base + s * 32);
            LDSM4(a1, base + 16 * ROWB + s * 32);
            #pragma unroll
            for (int j = 0; j < 4; j++) {
                MMA16816(dacc[0][j], a0, bF[s][j]);
                MMA16816(dacc[1][j], a1, bF[s][j]);
            }
            if ((s & 3) == 0 && hasNext)
                conv_chunk(rawB, rAother, el, q, s >> 2);
        }

        #pragma unroll
        for (int t = 0; t < 2; t++) {
            float p0 = 0.0f, p1 = 0.0f;
            #pragma unroll
            for (int j = 0; j < 4; j++) {
                p0 += fmaxf(dacc[t][j][0] + bb[j][0], 0.0f) * ww[j][0];
                p0 += fmaxf(dacc[t][j][1] + bb[j][1], 0.0f) * ww[j][1];
                p1 += fmaxf(dacc[t][j][2] + bb[j][0], 0.0f) * ww[j][0];
                p1 += fmaxf(dacc[t][j][3] + bb[j][1], 0.0f) * ww[j][1];
            }
            p0 += __shfl_xor_sync(0xffffffffu, p0, 1);
            p0 += __shfl_xor_sync(0xffffffffu, p0, 2);
            p1 += __shfl_xor_sync(0xffffffffu, p1, 1);
            p1 += __shfl_xor_sync(0xffffffffu, p1, 2);
            if ((lane & 3) == 0) {
                int r = mw * 32 + 16 * t + (lane >> 2);
                sred[r + 128 * nw]     = p0;
                sred[r + 8 + 128 * nw] = p1;
            }
        }
        __syncthreads();

        int tnn = tile + 2 * G;
        if (tnn < ETILES) {
            const char* sN = (const char*)(Hh + (size_t)n2 * 64);
            #pragma unroll
            for (int k = 0; k < 8; k++) CP16(rawDst + k * 16, sN + k * 16);
            CP_COMMIT();
            int tnnn = tile + 3 * G;
            if (tnnn < ETILES) n2 = __ldg(&idxp[tnnn * ET + el]);
        }

        {
            int ei = tid & 127;
            float l = sred[ei] + sred[ei + 128] + be2v;
            if (tid < 128) logits[e0 + ei] = l;
            else           probs[e0 + ei]  = 1.0f / (1.0f + __expf(-l));
        }
        b ^= 1;
    }
}

// ======================= launcher =======================
extern "C" void kernel_launch(void* const* d_in, const int* in_sizes, int n_in,
                              void* d_out, int out_size) {
    const float* x   = (const float*)d_in[0];
    const float* W1  = (const float*)d_in[1];
    const float* b1  = (const float*)d_in[2];
    const float* W2  = (const float*)d_in[3];
    const float* b2  = (const float*)d_in[4];
    const float* We1 = (const float*)d_in[5];
    const float* be1 = (const float*)d_in[6];
    const float* We2 = (const float*)d_in[7];
    const float* be2 = (const float*)d_in[8];
    const int*   ei  = (const int*)d_in[9];
    const int* src = ei;
    const int* dst = ei + NE;

    float* out    = (float*)d_out;
    float* H      = out;                 // [NN, 64]
    float* logits = out + NN * HID;      // [NE]
    float* probs  = logits + NE;         // [NE]

    void *yp, *h1p, *y2p, *zp, *hhp, *y16p;
    cudaGetSymbolAddress(&yp, g_y);
    cudaGetSymbolAddress(&h1p, g_h1);
    cudaGetSymbolAddress(&y2p, g_y2);
    cudaGetSymbolAddress(&zp, g_zeros);
    cudaGetSymbolAddress(&hhp, g_Hh);
    cudaGetSymbolAddress(&y16p, g_y16);

    int sm128 = (64 * (INDIM + 4) + 20 * (2 * INDIM + 8)) * (int)sizeof(float);
    int sm64  = (64 * (HID + 4)   + 20 * (2 * HID + 8))   * (int)sizeof(float);
    cudaFuncSetAttribute(k_fk1,
                         cudaFuncAttributeMaxDynamicSharedMemorySize, sm128);
    cudaFuncSetAttribute(k_gemm<HID>,
                         cudaFuncAttributeMaxDynamicSharedMemorySize, sm64);

    // FK1: gemm layer1 (y = x@W1, fp32 + fp16) + edge-count histogram
    k_fk1<<<G1BLK + CNTBLK, GNT, sm128>>>(x, W1, dst, (float*)yp, (__half*)y16p);
    // CSR scan + bucket
    k_scan1<<<NSCH, 1024>>>();
    k_scan23<<<NSCH, 1024>>>();
    k_bucket<<<(NE + 1023) / 1024, 1024>>>(src, dst);
    // layer 1 aggregation (fp16 neighbor gather), layer 2 gemm (fp32+fp16)
    k_aggrT<false><<<NN / 16, 256>>>((const float*)yp, (const __half*)y16p,
                                     b1, (float*)h1p, nullptr);
    k_gemm<HID><<<NN / GRT, GNT, sm64>>>((const float*)h1p, W2, (const float*)zp,
                                         (float*)y2p, (__half*)y16p);
    // layer-2 aggregation: fp16 gather; writes H fp32 (d_out) + fp16 (edge)
    k_aggrT<true><<<NN / 16, 256>>>((const float*)y2p, (const __half*)y16p,
                                    b2, H, (__half*)hhp);

    // fused edge MLP (fp16-H gather, interleaved pipelined mma.sync, K=256)
    cudaFuncSetAttribute(k_edge, cudaFuncAttributeMaxDynamicSharedMemorySize,
                         SMEM_EDGE);
    k_edge<<<148, 256, SMEM_EDGE>>>((const __half*)hhp, src, dst, We1, be1,
                                    We2, be2, logits, probs);
}